// round 15
// baseline (speedup 1.0000x reference)
#include <cuda_runtime.h>
#include <cuda_fp16.h>
#include <cstdint>

// Problem constants (fixed shapes from reference_code)
#define BB 2
#define SS 2048
#define DM 1024
#define NH 16
#define HD 64
#define MTOT (BB * SS)   // 4096

// Scratch (static device arrays: allocation-free)
__device__ __half g_Ah[3 * MTOT * DM];
__device__ __half g_Al[MTOT * DM];          // lo only needed for q (z=0)
__device__ __half g_WTh[3 * DM * DM];
// projected Q/K/V: hi for all, lo only for z=0 (Q). Q is pre-scaled by 1/8.
__device__ __half g_Ph[3 * MTOT * DM];
__device__ __half g_Pl[MTOT * DM];

// ===========================================================================
// PTX helpers
// ===========================================================================
__device__ __forceinline__ uint32_t smem_u32(const void* p) {
    uint32_t a;
    asm("{ .reg .u64 t; cvta.to.shared.u64 t, %1; cvt.u32.u64 %0, t; }"
        : "=r"(a) : "l"(p));
    return a;
}
__device__ __forceinline__ void cp_async16(uint32_t dst, const void* src) {
    asm volatile("cp.async.ca.shared.global [%0], [%1], 16;"
                 :: "r"(dst), "l"(src) : "memory");
}
#define CP_COMMIT() asm volatile("cp.async.commit_group;" ::: "memory")
#define CP_WAIT(n)  asm volatile("cp.async.wait_group %0;" :: "n"(n) : "memory")

__device__ __forceinline__ void ldsm_x4(uint32_t r[4], uint32_t addr) {
    asm volatile("ldmatrix.sync.aligned.m8n8.x4.shared.b16 {%0,%1,%2,%3}, [%4];"
                 : "=r"(r[0]), "=r"(r[1]), "=r"(r[2]), "=r"(r[3]) : "r"(addr));
}
__device__ __forceinline__ void ldsm_x2(uint32_t r[2], uint32_t addr) {
    asm volatile("ldmatrix.sync.aligned.m8n8.x2.shared.b16 {%0,%1}, [%2];"
                 : "=r"(r[0]), "=r"(r[1]) : "r"(addr));
}
__device__ __forceinline__ void ldsm_x4_t(uint32_t r[4], uint32_t addr) {
    asm volatile("ldmatrix.sync.aligned.m8n8.x4.trans.shared.b16 {%0,%1,%2,%3}, [%4];"
                 : "=r"(r[0]), "=r"(r[1]), "=r"(r[2]), "=r"(r[3]) : "r"(addr));
}
__device__ __forceinline__ void mma_f16(float d[4], const uint32_t a[4],
                                        const uint32_t b[2]) {
    asm volatile(
        "mma.sync.aligned.m16n8k16.row.col.f32.f16.f16.f32 "
        "{%0,%1,%2,%3}, {%4,%5,%6,%7}, {%8,%9}, {%0,%1,%2,%3};"
        : "+f"(d[0]), "+f"(d[1]), "+f"(d[2]), "+f"(d[3])
        : "r"(a[0]), "r"(a[1]), "r"(a[2]), "r"(a[3]), "r"(b[0]), "r"(b[1]));
}

// ===========================================================================
// Split pass 1: q/k/v fp32 -> fp16 hi (all three); lo only for q.
// ===========================================================================
__global__ __launch_bounds__(256)
void split_A(const float* __restrict__ q, const float* __restrict__ k,
             const float* __restrict__ v) {
    const size_t per = (size_t)MTOT * DM / 4;
    size_t idx = (size_t)blockIdx.x * 256 + threadIdx.x;
    if (idx >= 3 * per) return;
    const int m = (int)(idx / per);
    const size_t off = idx - (size_t)m * per;
    const float4* src = (const float4*)(m == 0 ? q : (m == 1 ? k : v));
    float4 x = src[off];

    __half h0 = __float2half_rn(x.x), h1 = __float2half_rn(x.y);
    __half h2 = __float2half_rn(x.z), h3 = __float2half_rn(x.w);

    __half2* dh = (__half2*)g_Ah;
    dh[idx * 2]     = __halves2half2(h0, h1);
    dh[idx * 2 + 1] = __halves2half2(h2, h3);

    if (m == 0) {   // lo only for q
        __half l0 = __float2half_rn(x.x - __half2float(h0));
        __half l1 = __float2half_rn(x.y - __half2float(h1));
        __half l2 = __float2half_rn(x.z - __half2float(h2));
        __half l3 = __float2half_rn(x.w - __half2float(h3));
        __half2* dl = (__half2*)g_Al;
        dl[off * 2]     = __halves2half2(l0, l1);
        dl[off * 2 + 1] = __halves2half2(l2, l3);
    }
}

// ===========================================================================
// Split pass 2: W [K][N] -> W^T [N][K] fp16 hi (tiled smem transpose).
// ===========================================================================
__global__ __launch_bounds__(256)
void split_WT(const float* __restrict__ Wq, const float* __restrict__ Wk,
              const float* __restrict__ Wv) {
    __shared__ float tile[32][33];
    const int z = blockIdx.z;
    const float* W = (z == 0 ? Wq : (z == 1 ? Wk : Wv));
    const int n0 = blockIdx.x * 32;
    const int k0 = blockIdx.y * 32;
    const int tx = threadIdx.x, ty = threadIdx.y;

#pragma unroll
    for (int i = 0; i < 4; i++) {
        const int kk = k0 + ty + i * 8;
        tile[ty + i * 8][tx] = W[(size_t)kk * DM + n0 + tx];
    }
    __syncthreads();
    __half* outh = g_WTh + (size_t)z * DM * DM;
#pragma unroll
    for (int i = 0; i < 4; i++) {
        const int n = n0 + ty + i * 8;
        outh[(size_t)n * DM + k0 + tx] = __float2half_rn(tile[tx][ty + i * 8]);
    }
}

// ===========================================================================
// Tensor-core projection GEMM, fp16:
//   z==0 (Q): C = Ah*Bh + Al*Bh, pre-scaled 0.125, stored hi+lo.
//   z==1,2 (K,V): C = Ah*Bh only (output rounds to fp16 anyway), hi only.
// ===========================================================================
#define GST   144
#define ARR_B (128 * GST)              // 18432
#define BUF_B (3 * ARR_B)              // 55296
#define GEMM_SMEM (2 * BUF_B)          // 110592

__global__ __launch_bounds__(256)
void gemm_f16tc() {
    extern __shared__ char smem[];
    const int z = blockIdx.z;
    const bool isQ = (z == 0);
    const __half* Ah = g_Ah + (size_t)z * MTOT * DM;
    const __half* Al = g_Al;                          // used only for z==0
    const __half* Bh = g_WTh + (size_t)z * DM * DM;
    __half* Ch = g_Ph + (size_t)z * MTOT * DM;
    __half* Cl = g_Pl;                                // used only for z==0

    const int m0 = blockIdx.y * 128;
    const int n0 = blockIdx.x * 128;
    const int tid = threadIdx.x;
    const int lane = tid & 31;
    const int wid = tid >> 5;
    const int wm = (wid & 1) * 64;
    const int wn = (wid >> 1) * 32;

    const uint32_t sb = smem_u32(smem);
    const int frow = tid >> 3;
    const int fch = tid & 7;

    auto fill = [&](int buf, int kc) {
        const uint32_t b0 = sb + buf * BUF_B;
#pragma unroll
        for (int p = 0; p < 4; p++) {
            const int r = frow + p * 32;
            const uint32_t doff = (uint32_t)(r * GST + fch * 16);
            const size_t ga = (size_t)(m0 + r) * DM + kc + fch * 8;
            const size_t gb = (size_t)(n0 + r) * DM + kc + fch * 8;
            cp_async16(b0 + doff,             Ah + ga);
            if (isQ) cp_async16(b0 + ARR_B + doff, Al + ga);
            cp_async16(b0 + 2 * ARR_B + doff, Bh + gb);
        }
        CP_COMMIT();
    };

    float d[4][4][4];
#pragma unroll
    for (int i = 0; i < 4; i++)
#pragma unroll
        for (int j = 0; j < 4; j++)
#pragma unroll
            for (int r = 0; r < 4; r++) d[i][j][r] = 0.f;

    const int aj = lane >> 3;
    const int arow_in = (aj & 1) * 8 + (lane & 7);
    const int akb = (aj >> 1) * 16;
    const int brow_in = (lane & 7);
    const int bkb = ((lane >> 3) & 1) * 16;

    fill(0, 0);
    int buf = 0;
    for (int s = 0; s < DM / 64; s++) {
        if (s + 1 < DM / 64) {
            fill(buf ^ 1, (s + 1) * 64);
            CP_WAIT(1);
        } else {
            CP_WAIT(0);
        }
        __syncthreads();

        const uint32_t base = sb + buf * BUF_B;
#pragma unroll
        for (int ks = 0; ks < 4; ks++) {
            const int k0b = ks * 32;
            uint32_t ah[4][4], al[4][4], bh[4][2];
#pragma unroll
            for (int mt = 0; mt < 4; mt++) {
                const uint32_t aoff =
                    (uint32_t)((wm + mt * 16 + arow_in) * GST + k0b + akb);
                ldsm_x4(ah[mt], base + aoff);
                if (isQ) ldsm_x4(al[mt], base + ARR_B + aoff);
            }
#pragma unroll
            for (int nt = 0; nt < 4; nt++) {
                const uint32_t boff =
                    (uint32_t)((wn + nt * 8 + brow_in) * GST + k0b + bkb);
                ldsm_x2(bh[nt], base + 2 * ARR_B + boff);
            }
#pragma unroll
            for (int mt = 0; mt < 4; mt++)
#pragma unroll
                for (int nt = 0; nt < 4; nt++) {
                    mma_f16(d[mt][nt], ah[mt], bh[nt]);
                    if (isQ) mma_f16(d[mt][nt], al[mt], bh[nt]);
                }
        }
        __syncthreads();
        buf ^= 1;
    }

    // epilogue: z==0 -> scale by 0.125, store hi+lo; else store hi only
    const float sc = isQ ? 0.125f : 1.0f;
    const int g = lane >> 2;
    const int t2 = (lane & 3) * 2;
#pragma unroll
    for (int mt = 0; mt < 4; mt++) {
#pragma unroll
        for (int nt = 0; nt < 4; nt++) {
            const int row0 = m0 + wm + mt * 16 + g;
            const int col = n0 + wn + nt * 8 + t2;
#pragma unroll
            for (int rr = 0; rr < 2; rr++) {
                const float a = d[mt][nt][rr * 2] * sc;
                const float bvl = d[mt][nt][rr * 2 + 1] * sc;
                const __half ha = __float2half_rn(a);
                const __half hb = __float2half_rn(bvl);
                const size_t o = (size_t)(row0 + rr * 8) * DM + col;
                *(__half2*)(Ch + o) = __halves2half2(ha, hb);
                if (isQ) {
                    *(__half2*)(Cl + o) = __halves2half2(
                        __float2half_rn(a - __half2float(ha)),
                        __float2half_rn(bvl - __half2float(hb)));
                }
            }
        }
    }
}

// ===========================================================================
// Tensor-core flash attention, fp16, no-max softmax (unchanged from R10).
// S  = Qh*Kh + Ql*Kh ; O += Ph*Vh ; l accumulated per-thread.
// ===========================================================================
#define AROW_B 144
#define TILE_SB (64 * AROW_B)          // 9216
#define STG_B (2 * TILE_SB)            // 18432
#define ATTN_SMEM (2 * STG_B + 2 * 256)

__global__ __launch_bounds__(128, 4)
void attn_tc(const int* __restrict__ v_mask, float* __restrict__ out) {
    extern __shared__ char dsm[];
    const uint32_t sb = smem_u32(dsm);
    int* smask = (int*)(dsm + 2 * STG_B);

    const int tid  = threadIdx.x;
    const int lane = tid & 31;
    const int w    = tid >> 5;
    const int q0   = blockIdx.x * 64;
    const int h    = blockIdx.y;
    const int b    = blockIdx.z;
    const int g    = lane >> 2;
    const int t    = lane & 3;

    const size_t ho = (size_t)h * HD;
    const __half* Qh_g = g_Ph + ((size_t)(b * SS)) * DM + ho;
    const __half* Ql_g = g_Pl + ((size_t)(b * SS)) * DM + ho;
    const __half* Kh_g = g_Ph + ((size_t)MTOT + b * SS) * DM + ho;
    const __half* Vh_g = g_Ph + ((size_t)2 * MTOT + b * SS) * DM + ho;

    // ---- Q phase: stage Qh/Ql through stage-0 {K, V} regions ----
#pragma unroll
    for (int i = 0; i < 8; i++) {
        const int c = tid + i * 128;
        const int tile = c >> 9;              // 0: Qh, 1: Ql
        const int cc = c & 511;
        const int row = cc >> 3;
        const int ch = cc & 7;
        const __half* src =
            (tile ? Ql_g : Qh_g) + (size_t)(q0 + row) * DM + ch * 8;
        cp_async16(sb + tile * TILE_SB + row * AROW_B + ch * 16, src);
    }
    CP_COMMIT(); CP_WAIT(0);
    __syncthreads();

    uint32_t qh[4][4], ql[4][4];
    {
        const uint32_t qrowoff = (uint32_t)((w * 16 + (lane & 15)) * AROW_B);
        const uint32_t qcoloff = (uint32_t)(((lane >> 4) & 1) * 16);
#pragma unroll
        for (int kc = 0; kc < 4; kc++) {
            ldsm_x4(qh[kc], sb + qrowoff + kc * 32 + qcoloff);
            ldsm_x4(ql[kc], sb + TILE_SB + qrowoff + kc * 32 + qcoloff);
        }
    }
    __syncthreads();

    float o[8][4];
#pragma unroll
    for (int j = 0; j < 8; j++)
#pragma unroll
        for (int r = 0; r < 4; r++) o[j][r] = 0.f;
    float l0 = 0.f, l1 = 0.f;      // per-thread partial row sums

    auto stage_kv = [&](int kbb, int s) {
        if (kbb < SS) {
            const uint32_t base = sb + s * STG_B;
#pragma unroll
            for (int i = 0; i < 8; i++) {
                const int c = tid + i * 128;
                const int tile = c >> 9;      // 0: Kh, 1: Vh
                const int cc = c & 511;
                const int row = cc >> 3;
                const int ch = cc & 7;
                const __half* src =
                    (tile ? Vh_g : Kh_g) + (size_t)(kbb + row) * DM + ch * 8;
                cp_async16(base + tile * TILE_SB + row * AROW_B + ch * 16, src);
            }
            if (tid < 16)
                cp_async16(sb + 2 * STG_B + s * 256 + tid * 16,
                           v_mask + b * SS + kbb + tid * 4);
        }
        CP_COMMIT();   // always commit so group depth stays fixed
    };

    const uint32_t krow = (uint32_t)((((lane >> 4) & 1) * 8 + (lane & 7)) * AROW_B);
    const uint32_t kcol = (uint32_t)(((lane >> 3) & 1) * 16);
    const uint32_t vrow = (uint32_t)((lane & 15) * AROW_B);
    const uint32_t vcol = (uint32_t)(((lane >> 4) & 1) * 16);

    stage_kv(0, 0);
    stage_kv(64, 1);

    for (int it = 0; it < SS / 64; it++) {
        const int s = it & 1;
        CP_WAIT(1);
        __syncthreads();
        const uint32_t bKh = sb + s * STG_B;
        const uint32_t bVh = bKh + TILE_SB;
        const int* msk = smask + s * 64;

        // ---- S = Qh K^T + Ql K^T (scores already scaled via Q) ----
        float sfr[8][4];
#pragma unroll
        for (int j = 0; j < 8; j++)
#pragma unroll
            for (int r = 0; r < 4; r++) sfr[j][r] = 0.f;
#pragma unroll
        for (int kc = 0; kc < 4; kc++) {
#pragma unroll
            for (int jp = 0; jp < 4; jp++) {
                uint32_t kh4[4];
                const uint32_t ao =
                    (uint32_t)(jp * 16 * AROW_B) + krow + kc * 32 + kcol;
                ldsm_x4(kh4, bKh + ao);
                mma_f16(sfr[2 * jp],     qh[kc], kh4);
                mma_f16(sfr[2 * jp],     ql[kc], kh4);
                mma_f16(sfr[2 * jp + 1], qh[kc], kh4 + 2);
                mma_f16(sfr[2 * jp + 1], ql[kc], kh4 + 2);
            }
        }

        // ---- mask -> exp -> partial l accumulation (no max tracking) ----
#pragma unroll
        for (int j = 0; j < 8; j++) {
            const int mk0 = msk[j * 8 + 2 * t];
            const int mk1 = msk[j * 8 + 2 * t + 1];
            sfr[j][0] = __expf(mk0 ? sfr[j][0] : -1e12f);
            sfr[j][1] = __expf(mk1 ? sfr[j][1] : -1e12f);
            sfr[j][2] = __expf(mk0 ? sfr[j][2] : -1e12f);
            sfr[j][3] = __expf(mk1 ? sfr[j][3] : -1e12f);
            l0 += sfr[j][0] + sfr[j][1];
            l1 += sfr[j][2] + sfr[j][3];
        }

        // ---- O += P V (P hi only, packed in registers) ----
#pragma unroll
        for (int kc = 0; kc < 4; kc++) {
            const int j0 = 2 * kc, j1 = 2 * kc + 1;
            uint32_t pah[4];
            {
                const float* ps[4] = {sfr[j0], sfr[j0] + 2, sfr[j1], sfr[j1] + 2};
#pragma unroll
                for (int r = 0; r < 4; r++) {
                    __half2 hp = __halves2half2(__float2half_rn(ps[r][0]),
                                                __float2half_rn(ps[r][1]));
                    pah[r] = *reinterpret_cast<uint32_t*>(&hp);
                }
            }
#pragma unroll
            for (int jp = 0; jp < 4; jp++) {
                uint32_t vh4[4];
                const uint32_t ao =
                    (uint32_t)(kc * 16 * AROW_B) + vrow + jp * 32 + vcol;
                ldsm_x4_t(vh4, bVh + ao);
                mma_f16(o[2 * jp],     pah, vh4);
                mma_f16(o[2 * jp + 1], pah, vh4 + 2);
            }
        }
        __syncthreads();              // all reads of stage s done
        stage_kv((it + 2) * 64, s);   // prefetch tile it+2 into stage s
    }

    // ---- epilogue: reduce l across the quad, normalize, write ----
    l0 += __shfl_xor_sync(0xffffffffu, l0, 1);
    l0 += __shfl_xor_sync(0xffffffffu, l0, 2);
    l1 += __shfl_xor_sync(0xffffffffu, l1, 1);
    l1 += __shfl_xor_sync(0xffffffffu, l1, 2);
    const float inv0 = 1.0f / l0, inv1 = 1.0f / l1;
    const int r0 = q0 + w * 16 + g;
    float* op0 = out + ((size_t)(b * SS) + r0) * DM + ho + 2 * t;
    float* op1 = op0 + (size_t)8 * DM;
#pragma unroll
    for (int j2 = 0; j2 < 8; j2++) {
        *(float2*)(op0 + j2 * 8) = make_float2(o[j2][0] * inv0, o[j2][1] * inv0);
        *(float2*)(op1 + j2 * 8) = make_float2(o[j2][2] * inv1, o[j2][3] * inv1);
    }
}

// ===========================================================================
// Launch
// ===========================================================================
extern "C" void kernel_launch(void* const* d_in, const int* in_sizes, int n_in,
                              void* d_out, int out_size) {
    const float* q  = (const float*)d_in[0];
    const float* k  = (const float*)d_in[1];
    const float* v  = (const float*)d_in[2];
    const int*   vm = (const int*)  d_in[3];
    const float* Wq = (const float*)d_in[4];
    const float* Wk = (const float*)d_in[5];
    const float* Wv = (const float*)d_in[6];
    float* out = (float*)d_out;

    const int nA = (int)(((size_t)3 * MTOT * DM / 4 + 255) / 256);
    split_A<<<nA, 256>>>(q, k, v);
    split_WT<<<dim3(DM / 32, DM / 32, 3), dim3(32, 8)>>>(Wq, Wk, Wv);

    cudaFuncSetAttribute(gemm_f16tc,
                         cudaFuncAttributeMaxDynamicSharedMemorySize, GEMM_SMEM);
    gemm_f16tc<<<dim3(DM / 128, MTOT / 128, 3), 256, GEMM_SMEM>>>();

    cudaFuncSetAttribute(attn_tc,
                         cudaFuncAttributeMaxDynamicSharedMemorySize, ATTN_SMEM);
    attn_tc<<<dim3(SS / 64, NH, BB), 128, ATTN_SMEM>>>(vm, out);
}

// round 16
// speedup vs baseline: 1.3984x; 1.3984x over previous
#include <cuda_runtime.h>
#include <cuda_fp16.h>
#include <cstdint>

// Problem constants (fixed shapes from reference_code)
#define BB 2
#define SS 2048
#define DM 1024
#define NH 16
#define HD 64
#define MTOT (BB * SS)   // 4096

// Scratch (static device arrays: allocation-free)
__device__ __half g_Ah[3 * MTOT * DM];      // fp16(q,k,v)
__device__ __half g_WTh[3 * DM * DM];       // fp16(W^T)
__device__ __half g_Ph[3 * MTOT * DM];      // projected Q(pre-scaled 1/8),K,V

// ===========================================================================
// PTX helpers
// ===========================================================================
__device__ __forceinline__ uint32_t smem_u32(const void* p) {
    uint32_t a;
    asm("{ .reg .u64 t; cvta.to.shared.u64 t, %1; cvt.u32.u64 %0, t; }"
        : "=r"(a) : "l"(p));
    return a;
}
__device__ __forceinline__ void cp_async16(uint32_t dst, const void* src) {
    asm volatile("cp.async.ca.shared.global [%0], [%1], 16;"
                 :: "r"(dst), "l"(src) : "memory");
}
#define CP_COMMIT() asm volatile("cp.async.commit_group;" ::: "memory")
#define CP_WAIT(n)  asm volatile("cp.async.wait_group %0;" :: "n"(n) : "memory")

__device__ __forceinline__ void ldsm_x4(uint32_t r[4], uint32_t addr) {
    asm volatile("ldmatrix.sync.aligned.m8n8.x4.shared.b16 {%0,%1,%2,%3}, [%4];"
                 : "=r"(r[0]), "=r"(r[1]), "=r"(r[2]), "=r"(r[3]) : "r"(addr));
}
__device__ __forceinline__ void ldsm_x2(uint32_t r[2], uint32_t addr) {
    asm volatile("ldmatrix.sync.aligned.m8n8.x2.shared.b16 {%0,%1}, [%2];"
                 : "=r"(r[0]), "=r"(r[1]) : "r"(addr));
}
__device__ __forceinline__ void ldsm_x4_t(uint32_t r[4], uint32_t addr) {
    asm volatile("ldmatrix.sync.aligned.m8n8.x4.trans.shared.b16 {%0,%1,%2,%3}, [%4];"
                 : "=r"(r[0]), "=r"(r[1]), "=r"(r[2]), "=r"(r[3]) : "r"(addr));
}
__device__ __forceinline__ void mma_f16(float d[4], const uint32_t a[4],
                                        const uint32_t b[2]) {
    asm volatile(
        "mma.sync.aligned.m16n8k16.row.col.f32.f16.f16.f32 "
        "{%0,%1,%2,%3}, {%4,%5,%6,%7}, {%8,%9}, {%0,%1,%2,%3};"
        : "+f"(d[0]), "+f"(d[1]), "+f"(d[2]), "+f"(d[3])
        : "r"(a[0]), "r"(a[1]), "r"(a[2]), "r"(a[3]), "r"(b[0]), "r"(b[1]));
}

// ===========================================================================
// Split pass 1: q/k/v fp32 -> fp16 (hi only).
// ===========================================================================
__global__ __launch_bounds__(256)
void split_A(const float* __restrict__ q, const float* __restrict__ k,
             const float* __restrict__ v) {
    const size_t per = (size_t)MTOT * DM / 4;
    size_t idx = (size_t)blockIdx.x * 256 + threadIdx.x;
    if (idx >= 3 * per) return;
    const int m = (int)(idx / per);
    const size_t off = idx - (size_t)m * per;
    const float4* src = (const float4*)(m == 0 ? q : (m == 1 ? k : v));
    float4 x = src[off];

    __half2* dh = (__half2*)g_Ah;
    dh[idx * 2]     = __halves2half2(__float2half_rn(x.x), __float2half_rn(x.y));
    dh[idx * 2 + 1] = __halves2half2(__float2half_rn(x.z), __float2half_rn(x.w));
}

// ===========================================================================
// Split pass 2: W [K][N] -> W^T [N][K] fp16 (tiled smem transpose).
// ===========================================================================
__global__ __launch_bounds__(256)
void split_WT(const float* __restrict__ Wq, const float* __restrict__ Wk,
              const float* __restrict__ Wv) {
    __shared__ float tile[32][33];
    const int z = blockIdx.z;
    const float* W = (z == 0 ? Wq : (z == 1 ? Wk : Wv));
    const int n0 = blockIdx.x * 32;
    const int k0 = blockIdx.y * 32;
    const int tx = threadIdx.x, ty = threadIdx.y;

#pragma unroll
    for (int i = 0; i < 4; i++) {
        const int kk = k0 + ty + i * 8;
        tile[ty + i * 8][tx] = W[(size_t)kk * DM + n0 + tx];
    }
    __syncthreads();
    __half* outh = g_WTh + (size_t)z * DM * DM;
#pragma unroll
    for (int i = 0; i < 4; i++) {
        const int n = n0 + ty + i * 8;
        outh[(size_t)n * DM + k0 + tx] = __float2half_rn(tile[tx][ty + i * 8]);
    }
}

// ===========================================================================
// Tensor-core projection GEMM, fp16 single-term: C = Ah*Bh.
// (Outputs round to fp16; per measured error model each dropped correction
//  term costs ~3e-4 RSS on the final output.)
// 2 smem arrays per stage -> 73728 B total -> 3 CTAs/SM.
// z==0 (Q): output pre-scaled by 0.125.
// ===========================================================================
#define GST   144
#define ARR_B (128 * GST)              // 18432
#define BUF_B (2 * ARR_B)              // 36864
#define GEMM_SMEM (2 * BUF_B)          // 73728

__global__ __launch_bounds__(256)
void gemm_f16tc() {
    extern __shared__ char smem[];
    const int z = blockIdx.z;
    const __half* Ah = g_Ah + (size_t)z * MTOT * DM;
    const __half* Bh = g_WTh + (size_t)z * DM * DM;
    __half* Ch = g_Ph + (size_t)z * MTOT * DM;

    const int m0 = blockIdx.y * 128;
    const int n0 = blockIdx.x * 128;
    const int tid = threadIdx.x;
    const int lane = tid & 31;
    const int wid = tid >> 5;
    const int wm = (wid & 1) * 64;
    const int wn = (wid >> 1) * 32;

    const uint32_t sb = smem_u32(smem);
    const int frow = tid >> 3;
    const int fch = tid & 7;

    auto fill = [&](int buf, int kc) {
        const uint32_t b0 = sb + buf * BUF_B;
#pragma unroll
        for (int p = 0; p < 4; p++) {
            const int r = frow + p * 32;
            const uint32_t doff = (uint32_t)(r * GST + fch * 16);
            const size_t ga = (size_t)(m0 + r) * DM + kc + fch * 8;
            const size_t gb = (size_t)(n0 + r) * DM + kc + fch * 8;
            cp_async16(b0 + doff,         Ah + ga);
            cp_async16(b0 + ARR_B + doff, Bh + gb);
        }
        CP_COMMIT();
    };

    float d[4][4][4];
#pragma unroll
    for (int i = 0; i < 4; i++)
#pragma unroll
        for (int j = 0; j < 4; j++)
#pragma unroll
            for (int r = 0; r < 4; r++) d[i][j][r] = 0.f;

    const int aj = lane >> 3;
    const int arow_in = (aj & 1) * 8 + (lane & 7);
    const int akb = (aj >> 1) * 16;
    const int brow_in = (lane & 7);
    const int bkb = ((lane >> 3) & 1) * 16;

    fill(0, 0);
    int buf = 0;
    for (int s = 0; s < DM / 64; s++) {
        if (s + 1 < DM / 64) {
            fill(buf ^ 1, (s + 1) * 64);
            CP_WAIT(1);
        } else {
            CP_WAIT(0);
        }
        __syncthreads();

        const uint32_t base = sb + buf * BUF_B;
#pragma unroll
        for (int ks = 0; ks < 4; ks++) {
            const int k0b = ks * 32;
            uint32_t ah[4][4], bh[4][2];
#pragma unroll
            for (int mt = 0; mt < 4; mt++) {
                const uint32_t aoff =
                    (uint32_t)((wm + mt * 16 + arow_in) * GST + k0b + akb);
                ldsm_x4(ah[mt], base + aoff);
            }
#pragma unroll
            for (int nt = 0; nt < 4; nt++) {
                const uint32_t boff =
                    (uint32_t)((wn + nt * 8 + brow_in) * GST + k0b + bkb);
                ldsm_x2(bh[nt], base + ARR_B + boff);
            }
#pragma unroll
            for (int mt = 0; mt < 4; mt++)
#pragma unroll
                for (int nt = 0; nt < 4; nt++)
                    mma_f16(d[mt][nt], ah[mt], bh[nt]);
        }
        __syncthreads();
        buf ^= 1;
    }

    // epilogue: z==0 -> scale by 0.125; store fp16
    const float sc = (z == 0) ? 0.125f : 1.0f;
    const int g = lane >> 2;
    const int t2 = (lane & 3) * 2;
#pragma unroll
    for (int mt = 0; mt < 4; mt++) {
#pragma unroll
        for (int nt = 0; nt < 4; nt++) {
            const int row0 = m0 + wm + mt * 16 + g;
            const int col = n0 + wn + nt * 8 + t2;
#pragma unroll
            for (int rr = 0; rr < 2; rr++) {
                const float a = d[mt][nt][rr * 2] * sc;
                const float bvl = d[mt][nt][rr * 2 + 1] * sc;
                const size_t o = (size_t)(row0 + rr * 8) * DM + col;
                *(__half2*)(Ch + o) =
                    __halves2half2(__float2half_rn(a), __float2half_rn(bvl));
            }
        }
    }
}

// ===========================================================================
// Tensor-core flash attention, fp16 single-term, no-max softmax.
// S = Qh*Kh ; O += Ph*Vh ; l accumulated per-thread, reduced in epilogue.
// Q carries the 1/8 scale; exp(-1e12)==0 handles masked keys exactly.
// ===========================================================================
#define AROW_B 144
#define TILE_SB (64 * AROW_B)          // 9216
#define STG_B (2 * TILE_SB)            // 18432
#define ATTN_SMEM (2 * STG_B + 2 * 256)

__global__ __launch_bounds__(128, 4)
void attn_tc(const int* __restrict__ v_mask, float* __restrict__ out) {
    extern __shared__ char dsm[];
    const uint32_t sb = smem_u32(dsm);
    int* smask = (int*)(dsm + 2 * STG_B);

    const int tid  = threadIdx.x;
    const int lane = tid & 31;
    const int w    = tid >> 5;
    const int q0   = blockIdx.x * 64;
    const int h    = blockIdx.y;
    const int b    = blockIdx.z;
    const int g    = lane >> 2;
    const int t    = lane & 3;

    const size_t ho = (size_t)h * HD;
    const __half* Qh_g = g_Ph + ((size_t)(b * SS)) * DM + ho;
    const __half* Kh_g = g_Ph + ((size_t)MTOT + b * SS) * DM + ho;
    const __half* Vh_g = g_Ph + ((size_t)2 * MTOT + b * SS) * DM + ho;

    // ---- Q phase: stage Qh through the stage-0 K region ----
#pragma unroll
    for (int i = 0; i < 4; i++) {
        const int c = tid + i * 128;          // 0..511
        const int row = c >> 3;
        const int ch = c & 7;
        cp_async16(sb + row * AROW_B + ch * 16,
                   Qh_g + (size_t)(q0 + row) * DM + ch * 8);
    }
    CP_COMMIT(); CP_WAIT(0);
    __syncthreads();

    uint32_t qh[4][4];
    {
        const uint32_t qrowoff = (uint32_t)((w * 16 + (lane & 15)) * AROW_B);
        const uint32_t qcoloff = (uint32_t)(((lane >> 4) & 1) * 16);
#pragma unroll
        for (int kc = 0; kc < 4; kc++)
            ldsm_x4(qh[kc], sb + qrowoff + kc * 32 + qcoloff);
    }
    __syncthreads();

    float o[8][4];
#pragma unroll
    for (int j = 0; j < 8; j++)
#pragma unroll
        for (int r = 0; r < 4; r++) o[j][r] = 0.f;
    float l0 = 0.f, l1 = 0.f;      // per-thread partial row sums

    auto stage_kv = [&](int kbb, int s) {
        if (kbb < SS) {
            const uint32_t base = sb + s * STG_B;
#pragma unroll
            for (int i = 0; i < 8; i++) {
                const int c = tid + i * 128;
                const int tile = c >> 9;      // 0: Kh, 1: Vh
                const int cc = c & 511;
                const int row = cc >> 3;
                const int ch = cc & 7;
                const __half* src =
                    (tile ? Vh_g : Kh_g) + (size_t)(kbb + row) * DM + ch * 8;
                cp_async16(base + tile * TILE_SB + row * AROW_B + ch * 16, src);
            }
            if (tid < 16)
                cp_async16(sb + 2 * STG_B + s * 256 + tid * 16,
                           v_mask + b * SS + kbb + tid * 4);
        }
        CP_COMMIT();   // always commit so group depth stays fixed
    };

    const uint32_t krow = (uint32_t)((((lane >> 4) & 1) * 8 + (lane & 7)) * AROW_B);
    const uint32_t kcol = (uint32_t)(((lane >> 3) & 1) * 16);
    const uint32_t vrow = (uint32_t)((lane & 15) * AROW_B);
    const uint32_t vcol = (uint32_t)(((lane >> 4) & 1) * 16);

    stage_kv(0, 0);
    stage_kv(64, 1);

    for (int it = 0; it < SS / 64; it++) {
        const int s = it & 1;
        CP_WAIT(1);
        __syncthreads();
        const uint32_t bKh = sb + s * STG_B;
        const uint32_t bVh = bKh + TILE_SB;
        const int* msk = smask + s * 64;

        // ---- S = Qh K^T (scores already scaled via Q) ----
        float sfr[8][4];
#pragma unroll
        for (int j = 0; j < 8; j++)
#pragma unroll
            for (int r = 0; r < 4; r++) sfr[j][r] = 0.f;
#pragma unroll
        for (int kc = 0; kc < 4; kc++) {
#pragma unroll
            for (int jp = 0; jp < 4; jp++) {
                uint32_t kh4[4];
                const uint32_t ao =
                    (uint32_t)(jp * 16 * AROW_B) + krow + kc * 32 + kcol;
                ldsm_x4(kh4, bKh + ao);
                mma_f16(sfr[2 * jp],     qh[kc], kh4);
                mma_f16(sfr[2 * jp + 1], qh[kc], kh4 + 2);
            }
        }

        // ---- mask -> exp -> partial l accumulation (no max tracking) ----
#pragma unroll
        for (int j = 0; j < 8; j++) {
            const int mk0 = msk[j * 8 + 2 * t];
            const int mk1 = msk[j * 8 + 2 * t + 1];
            sfr[j][0] = __expf(mk0 ? sfr[j][0] : -1e12f);
            sfr[j][1] = __expf(mk1 ? sfr[j][1] : -1e12f);
            sfr[j][2] = __expf(mk0 ? sfr[j][2] : -1e12f);
            sfr[j][3] = __expf(mk1 ? sfr[j][3] : -1e12f);
            l0 += sfr[j][0] + sfr[j][1];
            l1 += sfr[j][2] + sfr[j][3];
        }

        // ---- O += P V (P hi only, packed in registers) ----
#pragma unroll
        for (int kc = 0; kc < 4; kc++) {
            const int j0 = 2 * kc, j1 = 2 * kc + 1;
            uint32_t pah[4];
            {
                const float* ps[4] = {sfr[j0], sfr[j0] + 2, sfr[j1], sfr[j1] + 2};
#pragma unroll
                for (int r = 0; r < 4; r++) {
                    __half2 hp = __halves2half2(__float2half_rn(ps[r][0]),
                                                __float2half_rn(ps[r][1]));
                    pah[r] = *reinterpret_cast<uint32_t*>(&hp);
                }
            }
#pragma unroll
            for (int jp = 0; jp < 4; jp++) {
                uint32_t vh4[4];
                const uint32_t ao =
                    (uint32_t)(kc * 16 * AROW_B) + vrow + jp * 32 + vcol;
                ldsm_x4_t(vh4, bVh + ao);
                mma_f16(o[2 * jp],     pah, vh4);
                mma_f16(o[2 * jp + 1], pah, vh4 + 2);
            }
        }
        __syncthreads();              // all reads of stage s done
        stage_kv((it + 2) * 64, s);   // prefetch tile it+2 into stage s
    }

    // ---- epilogue: reduce l across the quad, normalize, write ----
    l0 += __shfl_xor_sync(0xffffffffu, l0, 1);
    l0 += __shfl_xor_sync(0xffffffffu, l0, 2);
    l1 += __shfl_xor_sync(0xffffffffu, l1, 1);
    l1 += __shfl_xor_sync(0xffffffffu, l1, 2);
    const float inv0 = 1.0f / l0, inv1 = 1.0f / l1;
    const int r0 = q0 + w * 16 + g;
    float* op0 = out + ((size_t)(b * SS) + r0) * DM + ho + 2 * t;
    float* op1 = op0 + (size_t)8 * DM;
#pragma unroll
    for (int j2 = 0; j2 < 8; j2++) {
        *(float2*)(op0 + j2 * 8) = make_float2(o[j2][0] * inv0, o[j2][1] * inv0);
        *(float2*)(op1 + j2 * 8) = make_float2(o[j2][2] * inv1, o[j2][3] * inv1);
    }
}

// ===========================================================================
// Launch
// ===========================================================================
extern "C" void kernel_launch(void* const* d_in, const int* in_sizes, int n_in,
                              void* d_out, int out_size) {
    const float* q  = (const float*)d_in[0];
    const float* k  = (const float*)d_in[1];
    const float* v  = (const float*)d_in[2];
    const int*   vm = (const int*)  d_in[3];
    const float* Wq = (const float*)d_in[4];
    const float* Wk = (const float*)d_in[5];
    const float* Wv = (const float*)d_in[6];
    float* out = (float*)d_out;

    const int nA = (int)(((size_t)3 * MTOT * DM / 4 + 255) / 256);
    split_A<<<nA, 256>>>(q, k, v);
    split_WT<<<dim3(DM / 32, DM / 32, 3), dim3(32, 8)>>>(Wq, Wk, Wv);

    cudaFuncSetAttribute(gemm_f16tc,
                         cudaFuncAttributeMaxDynamicSharedMemorySize, GEMM_SMEM);
    gemm_f16tc<<<dim3(DM / 128, MTOT / 128, 3), 256, GEMM_SMEM>>>();

    cudaFuncSetAttribute(attn_tc,
                         cudaFuncAttributeMaxDynamicSharedMemorySize, ATTN_SMEM);
    attn_tc<<<dim3(SS / 64, NH, BB), 128, ATTN_SMEM>>>(vm, out);
}